// round 2
// baseline (speedup 1.0000x reference)
#include <cuda_runtime.h>

static constexpr int Bb = 256;
static constexpr int Aa = 32;
static constexpr int Dd = 2048;

// Scratch for aggregated global-node input (allocation-free rule: __device__ global)
__device__ float g_agg[Bb * Dd];
__device__ int g_label_is_i64;

// ---------------------------------------------------------------------------
// Detect label dtype layout: int64 stores 0/1 values as (low=val, high=0).
// If all odd 32-bit words of the first 128 words are zero -> int64.
// ---------------------------------------------------------------------------
__global__ void detect_label_kernel(const int* __restrict__ label32) {
    unsigned lane = threadIdx.x;           // 0..31
    int nz = 0;
    // check odd words 1,3,...,127 (covers first 64 logical int64 labels)
    for (int i = lane; i < 64; i += 32) {
        if (label32[2 * i + 1] != 0) nz = 1;
    }
    unsigned any = __ballot_sync(0xffffffffu, nz);
    if (lane == 0) g_label_is_i64 = (any == 0u) ? 1 : 0;
}

// ---------------------------------------------------------------------------
// Masked aggregation: g_agg[b, :] = sum over active attributes of feat[b,a,:]
// One block per batch sample, vectorized float4 streaming.
// ---------------------------------------------------------------------------
__global__ __launch_bounds__(256) void agg_kernel(
    const float* __restrict__ feat,
    const void* __restrict__ label_raw)
{
    int b = blockIdx.x;
    __shared__ unsigned s_mask;

    if (threadIdx.x < 32) {
        int pred;
        if (g_label_is_i64) {
            const long long* l = (const long long*)label_raw;
            pred = (l[(size_t)b * Aa + threadIdx.x] > 0);
        } else {
            const int* l = (const int*)label_raw;
            pred = (l[(size_t)b * Aa + threadIdx.x] > 0);
        }
        unsigned m = __ballot_sync(0xffffffffu, pred);
        if (threadIdx.x == 0) s_mask = m;
    }
    __syncthreads();
    unsigned mask = s_mask;

    const float4* f4 = reinterpret_cast<const float4*>(feat) + (size_t)b * Aa * (Dd / 4);
    float4* o4 = reinterpret_cast<float4*>(g_agg) + (size_t)b * (Dd / 4);

    for (int i = threadIdx.x; i < Dd / 4; i += blockDim.x) {
        float4 s = make_float4(0.f, 0.f, 0.f, 0.f);
        unsigned mm = mask;
        while (mm) {
            int a = __ffs(mm) - 1;   // ascending order -> deterministic
            mm &= mm - 1;
            float4 v = f4[(size_t)a * (Dd / 4) + i];
            s.x += v.x; s.y += v.y; s.z += v.z; s.w += v.w;
        }
        o4[i] = s;
    }
}

// ---------------------------------------------------------------------------
// GEMM + bias + tanh:  out[256,2048] = tanh(g_agg @ W + bias)
// BM=BN=64, BK=16, 256 threads, 4x4 accum per thread, double-buffered SMEM.
// ---------------------------------------------------------------------------
static constexpr int BM = 64, BN = 64, BK = 16;

__global__ __launch_bounds__(256) void gemm_bias_tanh_kernel(
    const float* __restrict__ W,
    const float* __restrict__ bias,
    float* __restrict__ out)
{
    __shared__ float As[2][BK][BM + 4];   // A stored transposed [k][m]; stride 68 floats (16B-aligned rows)
    __shared__ float Bs[2][BK][BN];

    const int bx = blockIdx.x;   // N tile (0..31)
    const int by = blockIdx.y;   // M tile (0..3)
    const int tid = threadIdx.x;
    const int tx = tid & 15;     // N direction (0..15)
    const int ty = tid >> 4;     // M direction (0..15)

    // Global-load assignments (each thread loads exactly one float4 of A and B per BK tile)
    const int a_row  = tid >> 2;          // 0..63
    const int a_col4 = (tid & 3) * 4;     // 0,4,8,12
    const int b_row  = tid >> 4;          // 0..15
    const int b_col4 = (tid & 15) * 4;    // 0..60

    const float* Aptr = g_agg + (size_t)(by * BM + a_row) * Dd + a_col4;
    const float* Bptr = W + (size_t)b_row * 2048 + bx * BN + b_col4;

    float acc[4][4];
#pragma unroll
    for (int i = 0; i < 4; i++)
#pragma unroll
        for (int j = 0; j < 4; j++) acc[i][j] = 0.f;

    // Preload tile 0
    float4 av = *(const float4*)(Aptr);
    float4 bv = *(const float4*)(Bptr);
    {
        As[0][a_col4 + 0][a_row] = av.x;
        As[0][a_col4 + 1][a_row] = av.y;
        As[0][a_col4 + 2][a_row] = av.z;
        As[0][a_col4 + 3][a_row] = av.w;
        *(float4*)&Bs[0][b_row][b_col4] = bv;
    }
    __syncthreads();

    const int NT = Dd / BK;   // 128
    int cur = 0;
    for (int kt = 0; kt < NT; kt++) {
        if (kt + 1 < NT) {
            av = *(const float4*)(Aptr + (size_t)(kt + 1) * BK);
            bv = *(const float4*)(Bptr + (size_t)(kt + 1) * BK * 2048);
        }

#pragma unroll
        for (int k = 0; k < BK; k++) {
            float4 a4 = *(const float4*)&As[cur][k][ty * 4];
            float4 b4 = *(const float4*)&Bs[cur][k][tx * 4];
            float am[4] = {a4.x, a4.y, a4.z, a4.w};
            float bn[4] = {b4.x, b4.y, b4.z, b4.w};
#pragma unroll
            for (int i = 0; i < 4; i++)
#pragma unroll
                for (int j = 0; j < 4; j++)
                    acc[i][j] = fmaf(am[i], bn[j], acc[i][j]);
        }

        if (kt + 1 < NT) {
            int nxt = cur ^ 1;
            As[nxt][a_col4 + 0][a_row] = av.x;
            As[nxt][a_col4 + 1][a_row] = av.y;
            As[nxt][a_col4 + 2][a_row] = av.z;
            As[nxt][a_col4 + 3][a_row] = av.w;
            *(float4*)&Bs[nxt][b_row][b_col4] = bv;
            __syncthreads();
            cur = nxt;
        }
    }

    // Epilogue: bias + tanh, vectorized store
    const int row0 = by * BM + ty * 4;
    const int col0 = bx * BN + tx * 4;
    float4 bb = *(const float4*)&bias[col0];
#pragma unroll
    for (int i = 0; i < 4; i++) {
        float4 r;
        r.x = tanhf(acc[i][0] + bb.x);
        r.y = tanhf(acc[i][1] + bb.y);
        r.z = tanhf(acc[i][2] + bb.z);
        r.w = tanhf(acc[i][3] + bb.w);
        *(float4*)&out[(size_t)(row0 + i) * 2048 + col0] = r;
    }
}

// ---------------------------------------------------------------------------
// Launch. Input order per setup_inputs: x, attribute_feat, attribute_label, W, b
// x is mathematically unused (adj[A][A] == 0).
// ---------------------------------------------------------------------------
extern "C" void kernel_launch(void* const* d_in, const int* in_sizes, int n_in,
                              void* d_out, int out_size) {
    (void)in_sizes; (void)n_in; (void)out_size;
    const float* feat  = (const float*)d_in[1];
    const void*  label = d_in[2];
    const float* W     = (const float*)d_in[3];
    const float* bias  = (const float*)d_in[4];
    float* out = (float*)d_out;

    detect_label_kernel<<<1, 32>>>((const int*)label);
    agg_kernel<<<Bb, 256>>>(feat, label);
    dim3 grid(2048 / BN, Bb / BM);
    gemm_bias_tanh_kernel<<<grid, 256>>>(W, bias, out);
}

// round 4
// speedup vs baseline: 1.1234x; 1.1234x over previous
#include <cuda_runtime.h>
#include <cuda_bf16.h>
#include <cstdint>

static constexpr int Bb = 256;
static constexpr int Aa = 32;
static constexpr int Dd = 2048;

// ---------------- device scratch (allocation-free rule) ----------------
__device__ __nv_bfloat16 g_Ahi[Bb * Dd];
__device__ __nv_bfloat16 g_Alo[Bb * Dd];
__device__ __nv_bfloat16 g_Wthi[Dd * Dd];   // [n][k] transposed W, hi part
__device__ __nv_bfloat16 g_Wtlo[Dd * Dd];   // [n][k] lo part

// ---------------- PTX helpers (baseline sm_80+ features only) ----------
__device__ __forceinline__ uint32_t smem_u32(const void* p) {
    uint32_t a;
    asm("{ .reg .u64 t; cvta.to.shared.u64 t, %1; cvt.u32.u64 %0, t; }"
        : "=r"(a) : "l"(p));
    return a;
}
__device__ __forceinline__ void cp_async16(uint32_t dst, const void* src) {
    asm volatile("cp.async.cg.shared.global [%0], [%1], 16;"
                 :: "r"(dst), "l"(src) : "memory");
}
__device__ __forceinline__ void cp_commit() {
    asm volatile("cp.async.commit_group;" ::: "memory");
}
__device__ __forceinline__ void ldsm4(uint32_t& r0, uint32_t& r1, uint32_t& r2,
                                      uint32_t& r3, uint32_t addr) {
    asm volatile("ldmatrix.sync.aligned.m8n8.x4.shared.b16 {%0,%1,%2,%3}, [%4];"
                 : "=r"(r0), "=r"(r1), "=r"(r2), "=r"(r3) : "r"(addr));
}
__device__ __forceinline__ void mma16816(float* d, const uint32_t* a,
                                         uint32_t b0, uint32_t b1) {
    asm volatile(
        "mma.sync.aligned.m16n8k16.row.col.f32.bf16.bf16.f32 "
        "{%0,%1,%2,%3}, {%4,%5,%6,%7}, {%8,%9}, {%0,%1,%2,%3};"
        : "+f"(d[0]), "+f"(d[1]), "+f"(d[2]), "+f"(d[3])
        : "r"(a[0]), "r"(a[1]), "r"(a[2]), "r"(a[3]), "r"(b0), "r"(b1));
}

// ---------------------------------------------------------------------------
// prep: blocks [0,256) masked agg -> A_hi/A_lo bf16 (with inline label-dtype
//       detection); blocks [256,1280) W transpose+split -> Wt_hi/Wt_lo [n][k]
// ---------------------------------------------------------------------------
__global__ __launch_bounds__(256) void prep_kernel(
    const float* __restrict__ feat,
    const void* __restrict__ label_raw,
    const float* __restrict__ W)
{
    __shared__ float tile[64][65];
    __shared__ unsigned s_mask;
    int bid = blockIdx.x;

    if (bid < Bb) {
        int b = bid;
        if (threadIdx.x < 32) {
            // inline dtype-layout detection: int64 labels (values 0/1) have all
            // odd 32-bit words zero across the first 64 entries.
            const int* l32 = (const int*)label_raw;
            int nz = 0;
            for (int i = threadIdx.x; i < 64; i += 32)
                if (l32[2 * i + 1] != 0) nz = 1;
            unsigned any = __ballot_sync(0xffffffffu, nz);
            int is_i64 = (any == 0u);

            int pred;
            if (is_i64) {
                const long long* l = (const long long*)label_raw;
                pred = (l[(size_t)b * Aa + threadIdx.x] > 0);
            } else {
                const int* l = (const int*)label_raw;
                pred = (l[(size_t)b * Aa + threadIdx.x] > 0);
            }
            unsigned m = __ballot_sync(0xffffffffu, pred);
            if (threadIdx.x == 0) s_mask = m;
        }
        __syncthreads();
        unsigned mask = s_mask;

        const float4* f4 = reinterpret_cast<const float4*>(feat) + (size_t)b * Aa * (Dd / 4);
        __nv_bfloat162* hi2 = reinterpret_cast<__nv_bfloat162*>(g_Ahi + (size_t)b * Dd);
        __nv_bfloat162* lo2 = reinterpret_cast<__nv_bfloat162*>(g_Alo + (size_t)b * Dd);

        for (int i = threadIdx.x; i < Dd / 4; i += 256) {
            float4 s = make_float4(0.f, 0.f, 0.f, 0.f);
            unsigned mm = mask;
            while (mm) {
                int a = __ffs(mm) - 1;  mm &= mm - 1;
                float4 v = f4[(size_t)a * (Dd / 4) + i];
                s.x += v.x; s.y += v.y; s.z += v.z; s.w += v.w;
            }
            float vals[4] = {s.x, s.y, s.z, s.w};
            __nv_bfloat16 h[4], l[4];
#pragma unroll
            for (int j = 0; j < 4; j++) {
                h[j] = __float2bfloat16(vals[j]);
                l[j] = __float2bfloat16(vals[j] - __bfloat162float(h[j]));
            }
            hi2[i * 2 + 0] = __nv_bfloat162(h[0], h[1]);
            hi2[i * 2 + 1] = __nv_bfloat162(h[2], h[3]);
            lo2[i * 2 + 0] = __nv_bfloat162(l[0], l[1]);
            lo2[i * 2 + 1] = __nv_bfloat162(l[2], l[3]);
        }
    } else {
        int t = bid - Bb;
        int n0 = (t & 31) * 64;
        int k0 = (t >> 5) * 64;
        int c = threadIdx.x & 63;
        int r4 = threadIdx.x >> 6;
#pragma unroll
        for (int i = 0; i < 16; i++) {
            int r = i * 4 + r4;
            tile[r][c] = W[(size_t)(k0 + r) * Dd + (n0 + c)];
        }
        __syncthreads();
#pragma unroll
        for (int i = 0; i < 16; i++) {
            int nr = i * 4 + r4;
            float v = tile[c][nr];
            __nv_bfloat16 h = __float2bfloat16(v);
            __nv_bfloat16 l = __float2bfloat16(v - __bfloat162float(h));
            size_t o = (size_t)(n0 + nr) * Dd + (k0 + c);
            g_Wthi[o] = h;
            g_Wtlo[o] = l;
        }
    }
}

// ---------------------------------------------------------------------------
// Fused 3-term bf16 GEMM + bias + tanh via mma.sync (HMMA tensor path).
// CTA tile 64x64, 8 warps = 2(m) x 2(n) x 2(k16-split). K loop: 3 terms x 64
// chunks of k32 = 192 chunks, 4-stage cp.async pipeline.
// ---------------------------------------------------------------------------
static constexpr int STAGE_BYTES = 8192;     // A 4KB + B 4KB
static constexpr int NSTAGE = 4;
static constexpr int NCHUNK = 192;           // 3 * (2048/32)

__global__ __launch_bounds__(256, 1) void gemm_kernel(
    const float* __restrict__ bias, float* __restrict__ out)
{
    __shared__ __align__(128) char smbuf[NSTAGE * STAGE_BYTES];   // 32 KB
    const uint32_t sbase = smem_u32(smbuf);

    const int tid = threadIdx.x;
    const int lane = tid & 31;
    const int wid = tid >> 5;
    const int kw = wid >> 2;          // k16 half (0/1)
    const int wm = (wid >> 1) & 1;    // warp m
    const int wn = wid & 1;           // warp n

    const int m0 = blockIdx.y * 64;
    const int n0 = blockIdx.x * 64;

    // ldmatrix address offsets (within a stage's A / B region), XOR-swizzled
    const int g = lane >> 3;          // address group 0..3
    const int lr = lane & 7;
    uint32_t offA[2], offB[2];
#pragma unroll
    for (int mt = 0; mt < 2; mt++) {
        int row = wm * 32 + mt * 16 + (g & 1) * 8 + lr;
        int c = 2 * kw + (g >> 1);                     // 16B chunk within 64B row
        offA[mt] = row * 64 + ((c ^ ((row >> 1) & 3)) << 4);
    }
#pragma unroll
    for (int nt = 0; nt < 2; nt++) {
        int row = wn * 32 + nt * 16 + ((g >> 1) & 1) * 8 + lr;
        int c = 2 * kw + (g & 1);
        offB[nt] = row * 64 + ((c ^ ((row >> 1) & 3)) << 4);
    }

    // cp.async per-thread assignment: one 16B chunk of A and one of B per chunk
    const int ldrow = tid >> 2;                        // 0..63
    const int ldc = tid & 3;
    const uint32_t ldoff = ldrow * 64 + ((ldc ^ ((ldrow >> 1) & 3)) << 4);

    auto issue_load = [&](int chunk) {
        int term = chunk >> 6;
        const __nv_bfloat16* Ap = (term == 2) ? g_Alo : g_Ahi;
        const __nv_bfloat16* Bp = (term == 1) ? g_Wtlo : g_Wthi;
        int kt = (chunk & 63) * 32;
        uint32_t st = sbase + (chunk & (NSTAGE - 1)) * STAGE_BYTES;
        cp_async16(st + ldoff, Ap + (size_t)(m0 + ldrow) * Dd + kt + ldc * 8);
        cp_async16(st + 4096 + ldoff, Bp + (size_t)(n0 + ldrow) * Dd + kt + ldc * 8);
        cp_commit();
    };

    float acc[2][4][4];
#pragma unroll
    for (int mt = 0; mt < 2; mt++)
#pragma unroll
        for (int nf = 0; nf < 4; nf++)
#pragma unroll
            for (int k = 0; k < 4; k++) acc[mt][nf][k] = 0.f;

    issue_load(0); issue_load(1); issue_load(2);

    for (int i = 0; i < NCHUNK; i++) {
        asm volatile("cp.async.wait_group 2;" ::: "memory");
        __syncthreads();
        if (i + 3 < NCHUNK) issue_load(i + 3);

        uint32_t sA = sbase + (i & (NSTAGE - 1)) * STAGE_BYTES;
        uint32_t sB = sA + 4096;

        uint32_t a[2][4], b[2][4];
        ldsm4(a[0][0], a[0][1], a[0][2], a[0][3], sA + offA[0]);
        ldsm4(a[1][0], a[1][1], a[1][2], a[1][3], sA + offA[1]);
        ldsm4(b[0][0], b[0][1], b[0][2], b[0][3], sB + offB[0]);
        ldsm4(b[1][0], b[1][1], b[1][2], b[1][3], sB + offB[1]);

#pragma unroll
        for (int mt = 0; mt < 2; mt++) {
            mma16816(acc[mt][0], a[mt], b[0][0], b[0][1]);
            mma16816(acc[mt][1], a[mt], b[0][2], b[0][3]);
            mma16816(acc[mt][2], a[mt], b[1][0], b[1][1]);
            mma16816(acc[mt][3], a[mt], b[1][2], b[1][3]);
        }
    }
    asm volatile("cp.async.wait_group 0;" ::: "memory");
    __syncthreads();

    // split-k reduce through SMEM, then bias + tanh
    float* smf = (float*)smbuf;
    const int region = (wm * 2 + wn) * 1024;           // 32x32 floats per warp-pair

    if (kw == 1) {
#pragma unroll
        for (int mt = 0; mt < 2; mt++)
#pragma unroll
            for (int nf = 0; nf < 4; nf++) {
                int lrow = mt * 16 + (lane >> 2);
                int lcol = nf * 8 + (lane & 3) * 2;
                smf[region + lrow * 32 + lcol + 0] = acc[mt][nf][0];
                smf[region + lrow * 32 + lcol + 1] = acc[mt][nf][1];
                smf[region + (lrow + 8) * 32 + lcol + 0] = acc[mt][nf][2];
                smf[region + (lrow + 8) * 32 + lcol + 1] = acc[mt][nf][3];
            }
    }
    __syncthreads();
    if (kw == 0) {
#pragma unroll
        for (int mt = 0; mt < 2; mt++)
#pragma unroll
            for (int nf = 0; nf < 4; nf++) {
                int lrow = mt * 16 + (lane >> 2);
                int lcol = nf * 8 + (lane & 3) * 2;
                int grow = m0 + wm * 32 + lrow;
                int gcol = n0 + wn * 32 + lcol;

                float2 r0, r1;
                r0.x = tanhf(acc[mt][nf][0] + smf[region + lrow * 32 + lcol + 0] + bias[gcol + 0]);
                r0.y = tanhf(acc[mt][nf][1] + smf[region + lrow * 32 + lcol + 1] + bias[gcol + 1]);
                r1.x = tanhf(acc[mt][nf][2] + smf[region + (lrow + 8) * 32 + lcol + 0] + bias[gcol + 0]);
                r1.y = tanhf(acc[mt][nf][3] + smf[region + (lrow + 8) * 32 + lcol + 1] + bias[gcol + 1]);
                *(float2*)&out[(size_t)grow * Dd + gcol] = r0;
                *(float2*)&out[(size_t)(grow + 8) * Dd + gcol] = r1;
            }
    }
}

// ---------------------------------------------------------------------------
// launch: inputs x, attribute_feat, attribute_label, W, b  (x unused: adj[A][A]=0)
// ---------------------------------------------------------------------------
extern "C" void kernel_launch(void* const* d_in, const int* in_sizes, int n_in,
                              void* d_out, int out_size) {
    (void)in_sizes; (void)n_in; (void)out_size;
    const float* feat  = (const float*)d_in[1];
    const void*  label = d_in[2];
    const float* W     = (const float*)d_in[3];
    const float* bias  = (const float*)d_in[4];
    float* out = (float*)d_out;

    prep_kernel<<<Bb + 1024, 256>>>(feat, label, W);
    gemm_kernel<<<dim3(Dd / 64, Bb / 64), 256>>>(bias, out);
}

// round 6
// speedup vs baseline: 1.8546x; 1.6509x over previous
#include <cuda_runtime.h>
#include <cuda_bf16.h>
#include <cstdint>

static constexpr int Bb = 256;
static constexpr int Aa = 32;
static constexpr int Dd = 2048;

// ---------------- device scratch (allocation-free rule) ----------------
__device__ __nv_bfloat16 g_Ahi[Bb * Dd];
__device__ __nv_bfloat16 g_Alo[Bb * Dd];
__device__ __nv_bfloat16 g_Wthi[Dd * Dd];   // [n][k] transposed W, hi part
__device__ __nv_bfloat16 g_Wtlo[Dd * Dd];   // [n][k] lo part
__device__ float g_part[3][Bb * Dd];        // per-term fp32 partials

// ---------------- PTX helpers (baseline sm_80+ features only) ----------
__device__ __forceinline__ uint32_t smem_u32(const void* p) {
    uint32_t a;
    asm("{ .reg .u64 t; cvta.to.shared.u64 t, %1; cvt.u32.u64 %0, t; }"
        : "=r"(a) : "l"(p));
    return a;
}
__device__ __forceinline__ void cp_async16(uint32_t dst, const void* src) {
    asm volatile("cp.async.cg.shared.global [%0], [%1], 16;"
                 :: "r"(dst), "l"(src) : "memory");
}
__device__ __forceinline__ void cp_commit() {
    asm volatile("cp.async.commit_group;" ::: "memory");
}
__device__ __forceinline__ void ldsm4(uint32_t& r0, uint32_t& r1, uint32_t& r2,
                                      uint32_t& r3, uint32_t addr) {
    asm volatile("ldmatrix.sync.aligned.m8n8.x4.shared.b16 {%0,%1,%2,%3}, [%4];"
                 : "=r"(r0), "=r"(r1), "=r"(r2), "=r"(r3) : "r"(addr));
}
__device__ __forceinline__ void mma16816(float* d, const uint32_t* a,
                                         uint32_t b0, uint32_t b1) {
    asm volatile(
        "mma.sync.aligned.m16n8k16.row.col.f32.bf16.bf16.f32 "
        "{%0,%1,%2,%3}, {%4,%5,%6,%7}, {%8,%9}, {%0,%1,%2,%3};"
        : "+f"(d[0]), "+f"(d[1]), "+f"(d[2]), "+f"(d[3])
        : "r"(a[0]), "r"(a[1]), "r"(a[2]), "r"(a[3]), "r"(b0), "r"(b1));
}

// ---------------------------------------------------------------------------
// prep: blocks [0,256) masked agg -> A_hi/A_lo bf16 (with inline label-dtype
//       detection); blocks [256,1280) W transpose+split -> Wt_hi/Wt_lo [n][k]
// ---------------------------------------------------------------------------
__global__ __launch_bounds__(256) void prep_kernel(
    const float* __restrict__ feat,
    const void* __restrict__ label_raw,
    const float* __restrict__ W)
{
    __shared__ float tile[64][65];
    __shared__ unsigned s_mask;
    int bid = blockIdx.x;

    if (bid < Bb) {
        int b = bid;
        if (threadIdx.x < 32) {
            // int64 labels (values 0/1) have all odd 32-bit words zero
            const int* l32 = (const int*)label_raw;
            int nz = 0;
            for (int i = threadIdx.x; i < 64; i += 32)
                if (l32[2 * i + 1] != 0) nz = 1;
            unsigned any = __ballot_sync(0xffffffffu, nz);
            int is_i64 = (any == 0u);

            int pred;
            if (is_i64) {
                const long long* l = (const long long*)label_raw;
                pred = (l[(size_t)b * Aa + threadIdx.x] > 0);
            } else {
                const int* l = (const int*)label_raw;
                pred = (l[(size_t)b * Aa + threadIdx.x] > 0);
            }
            unsigned m = __ballot_sync(0xffffffffu, pred);
            if (threadIdx.x == 0) s_mask = m;
        }
        __syncthreads();
        unsigned mask = s_mask;

        const float4* f4 = reinterpret_cast<const float4*>(feat) + (size_t)b * Aa * (Dd / 4);
        __nv_bfloat162* hi2 = reinterpret_cast<__nv_bfloat162*>(g_Ahi + (size_t)b * Dd);
        __nv_bfloat162* lo2 = reinterpret_cast<__nv_bfloat162*>(g_Alo + (size_t)b * Dd);

        for (int i = threadIdx.x; i < Dd / 4; i += 256) {
            float4 s = make_float4(0.f, 0.f, 0.f, 0.f);
            unsigned mm = mask;
            while (mm) {
                int a = __ffs(mm) - 1;  mm &= mm - 1;
                float4 v = f4[(size_t)a * (Dd / 4) + i];
                s.x += v.x; s.y += v.y; s.z += v.z; s.w += v.w;
            }
            float vals[4] = {s.x, s.y, s.z, s.w};
            __nv_bfloat16 h[4], l[4];
#pragma unroll
            for (int j = 0; j < 4; j++) {
                h[j] = __float2bfloat16(vals[j]);
                l[j] = __float2bfloat16(vals[j] - __bfloat162float(h[j]));
            }
            hi2[i * 2 + 0] = __nv_bfloat162(h[0], h[1]);
            hi2[i * 2 + 1] = __nv_bfloat162(h[2], h[3]);
            lo2[i * 2 + 0] = __nv_bfloat162(l[0], l[1]);
            lo2[i * 2 + 1] = __nv_bfloat162(l[2], l[3]);
        }
    } else {
        int t = bid - Bb;
        int n0 = (t & 31) * 64;
        int k0 = (t >> 5) * 64;
        int c = threadIdx.x & 63;
        int r4 = threadIdx.x >> 6;
#pragma unroll
        for (int i = 0; i < 16; i++) {
            int r = i * 4 + r4;
            tile[r][c] = W[(size_t)(k0 + r) * Dd + (n0 + c)];
        }
        __syncthreads();
#pragma unroll
        for (int i = 0; i < 16; i++) {
            int nr = i * 4 + r4;
            float v = tile[c][nr];
            __nv_bfloat16 h = __float2bfloat16(v);
            __nv_bfloat16 l = __float2bfloat16(v - __bfloat162float(h));
            size_t o = (size_t)(n0 + nr) * Dd + (k0 + c);
            g_Wthi[o] = h;
            g_Wtlo[o] = l;
        }
    }
}

// ---------------------------------------------------------------------------
// bf16 GEMM via mma.sync, ONE split-term per CTA.z -> fp32 partials.
// CTA tile 64x64, 8 warps = 2(m) x 2(n) x 2(k16-split). K loop: 64 chunks
// of k32, 4-stage cp.async pipeline with EXACTLY ONE commit per iteration
// (empty commit in the tail) so wait_group 2 always covers the read stage.
// Grid 32x4x3 = 384 CTAs.
// ---------------------------------------------------------------------------
static constexpr int STAGE_BYTES = 8192;     // A 4KB + B 4KB
static constexpr int NSTAGE = 4;
static constexpr int NCHUNK = 64;            // 2048 / 32

__global__ __launch_bounds__(256, 1) void gemm_kernel() {
    __shared__ __align__(128) char smbuf[NSTAGE * STAGE_BYTES];   // 32 KB
    const uint32_t sbase = smem_u32(smbuf);

    const int tid = threadIdx.x;
    const int lane = tid & 31;
    const int wid = tid >> 5;
    const int kw = wid >> 2;          // k16 half (0/1)
    const int wm = (wid >> 1) & 1;    // warp m
    const int wn = wid & 1;           // warp n

    const int m0 = blockIdx.y * 64;
    const int n0 = blockIdx.x * 64;
    const int term = blockIdx.z;      // 0: Ahi*Whi, 1: Ahi*Wlo, 2: Alo*Whi

    const __nv_bfloat16* Ap = (term == 2) ? g_Alo : g_Ahi;
    const __nv_bfloat16* Bp = (term == 1) ? g_Wtlo : g_Wthi;
    const __nv_bfloat16* Ag = Ap + (size_t)m0 * Dd;
    const __nv_bfloat16* Bg = Bp + (size_t)n0 * Dd;

    // ldmatrix address offsets (within a stage's A / B region), XOR-swizzled
    const int g = lane >> 3;          // address group 0..3
    const int lr = lane & 7;
    uint32_t offA[2], offB[2];
#pragma unroll
    for (int mt = 0; mt < 2; mt++) {
        int row = wm * 32 + mt * 16 + (g & 1) * 8 + lr;
        int c = 2 * kw + (g >> 1);                     // 16B chunk within 64B row
        offA[mt] = row * 64 + ((c ^ ((row >> 1) & 3)) << 4);
    }
#pragma unroll
    for (int nt = 0; nt < 2; nt++) {
        int row = wn * 32 + nt * 16 + ((g >> 1) & 1) * 8 + lr;
        int c = 2 * kw + (g & 1);
        offB[nt] = row * 64 + ((c ^ ((row >> 1) & 3)) << 4);
    }

    // cp.async per-thread assignment: one 16B chunk of A and one of B per chunk
    const int ldrow = tid >> 2;                        // 0..63
    const int ldc = tid & 3;
    const uint32_t ldoff = ldrow * 64 + ((ldc ^ ((ldrow >> 1) & 3)) << 4);

    auto issue_load = [&](int chunk) {
        int kt = chunk * 32;
        uint32_t st = sbase + (chunk & (NSTAGE - 1)) * STAGE_BYTES;
        cp_async16(st + ldoff, Ag + (size_t)ldrow * Dd + kt + ldc * 8);
        cp_async16(st + 4096 + ldoff, Bg + (size_t)ldrow * Dd + kt + ldc * 8);
        cp_commit();
    };

    float acc[2][4][4];
#pragma unroll
    for (int mt = 0; mt < 2; mt++)
#pragma unroll
        for (int nf = 0; nf < 4; nf++)
#pragma unroll
            for (int k = 0; k < 4; k++) acc[mt][nf][k] = 0.f;

    issue_load(0); issue_load(1); issue_load(2);

    for (int i = 0; i < NCHUNK; i++) {
        // one commit-group per iteration (see tail 'else'): the group holding
        // chunk i was committed 3 iterations ago, so wait_group 2 (keep <=2
        // newest pending) guarantees stage i is fully landed -- incl. the tail.
        asm volatile("cp.async.wait_group 2;" ::: "memory");
        __syncthreads();
        if (i + 3 < NCHUNK) issue_load(i + 3);
        else cp_commit();                      // empty group keeps accounting exact

        uint32_t sA = sbase + (i & (NSTAGE - 1)) * STAGE_BYTES;
        uint32_t sB = sA + 4096;

        uint32_t a[2][4], b[2][4];
        ldsm4(a[0][0], a[0][1], a[0][2], a[0][3], sA + offA[0]);
        ldsm4(a[1][0], a[1][1], a[1][2], a[1][3], sA + offA[1]);
        ldsm4(b[0][0], b[0][1], b[0][2], b[0][3], sB + offB[0]);
        ldsm4(b[1][0], b[1][1], b[1][2], b[1][3], sB + offB[1]);

#pragma unroll
        for (int mt = 0; mt < 2; mt++) {
            mma16816(acc[mt][0], a[mt], b[0][0], b[0][1]);
            mma16816(acc[mt][1], a[mt], b[0][2], b[0][3]);
            mma16816(acc[mt][2], a[mt], b[1][0], b[1][1]);
            mma16816(acc[mt][3], a[mt], b[1][2], b[1][3]);
        }
    }
    asm volatile("cp.async.wait_group 0;" ::: "memory");
    __syncthreads();

    // split-k reduce through SMEM, then write fp32 partial for this term
    float* smf = (float*)smbuf;
    const int region = (wm * 2 + wn) * 1024;           // 32x32 floats per warp-pair
    float* gp = g_part[term];

    if (kw == 1) {
#pragma unroll
        for (int mt = 0; mt < 2; mt++)
#pragma unroll
            for (int nf = 0; nf < 4; nf++) {
                int lrow = mt * 16 + (lane >> 2);
                int lcol = nf * 8 + (lane & 3) * 2;
                smf[region + lrow * 32 + lcol + 0] = acc[mt][nf][0];
                smf[region + lrow * 32 + lcol + 1] = acc[mt][nf][1];
                smf[region + (lrow + 8) * 32 + lcol + 0] = acc[mt][nf][2];
                smf[region + (lrow + 8) * 32 + lcol + 1] = acc[mt][nf][3];
            }
    }
    __syncthreads();
    if (kw == 0) {
#pragma unroll
        for (int mt = 0; mt < 2; mt++)
#pragma unroll
            for (int nf = 0; nf < 4; nf++) {
                int lrow = mt * 16 + (lane >> 2);
                int lcol = nf * 8 + (lane & 3) * 2;
                int grow = m0 + wm * 32 + lrow;
                int gcol = n0 + wn * 32 + lcol;

                float2 r0, r1;
                r0.x = acc[mt][nf][0] + smf[region + lrow * 32 + lcol + 0];
                r0.y = acc[mt][nf][1] + smf[region + lrow * 32 + lcol + 1];
                r1.x = acc[mt][nf][2] + smf[region + (lrow + 8) * 32 + lcol + 0];
                r1.y = acc[mt][nf][3] + smf[region + (lrow + 8) * 32 + lcol + 1];
                *(float2*)&gp[(size_t)grow * Dd + gcol] = r0;
                *(float2*)&gp[(size_t)(grow + 8) * Dd + gcol] = r1;
            }
    }
}

// ---------------------------------------------------------------------------
// finish: out = tanh(p0 + p1 + p2 + bias)
// ---------------------------------------------------------------------------
__global__ __launch_bounds__(256) void finish_kernel(
    const float* __restrict__ bias, float* __restrict__ out)
{
    int idx = blockIdx.x * 256 + threadIdx.x;        // float4 index
    const float4* p0 = (const float4*)g_part[0];
    const float4* p1 = (const float4*)g_part[1];
    const float4* p2 = (const float4*)g_part[2];
    int n4 = idx & (Dd / 4 - 1);
    float4 a = p0[idx], b = p1[idx], c = p2[idx];
    float4 bv = ((const float4*)bias)[n4];
    float4 r;
    r.x = tanhf(a.x + b.x + c.x + bv.x);
    r.y = tanhf(a.y + b.y + c.y + bv.y);
    r.z = tanhf(a.z + b.z + c.z + bv.z);
    r.w = tanhf(a.w + b.w + c.w + bv.w);
    ((float4*)out)[idx] = r;
}

// ---------------------------------------------------------------------------
// launch: inputs x, attribute_feat, attribute_label, W, b  (x unused: adj[A][A]=0)
// ---------------------------------------------------------------------------
extern "C" void kernel_launch(void* const* d_in, const int* in_sizes, int n_in,
                              void* d_out, int out_size) {
    (void)in_sizes; (void)n_in; (void)out_size;
    const float* feat  = (const float*)d_in[1];
    const void*  label = d_in[2];
    const float* W     = (const float*)d_in[3];
    const float* bias  = (const float*)d_in[4];
    float* out = (float*)d_out;

    prep_kernel<<<Bb + 1024, 256>>>(feat, label, W);
    gemm_kernel<<<dim3(Dd / 64, Bb / 64, 3), 256>>>();
    finish_kernel<<<(Bb * Dd / 4) / 256, 256>>>(bias, out);
}

// round 8
// speedup vs baseline: 2.3749x; 1.2806x over previous
#include <cuda_runtime.h>
#include <cuda_bf16.h>
#include <cstdint>

static constexpr int Bb = 256;
static constexpr int Aa = 32;
static constexpr int Dd = 2048;

// ---------------- device scratch (allocation-free rule) ----------------
__device__ __nv_bfloat16 g_Ahi[Bb * Dd];
__device__ __nv_bfloat16 g_Alo[Bb * Dd];
__device__ __nv_bfloat16 g_Whi[Dd * Dd];    // [k][n] native layout, hi part
__device__ __nv_bfloat16 g_Wlo[Dd * Dd];    // [k][n] native layout, lo part
__device__ float g_part[3][Bb * Dd];        // per-term fp32 partials

// ---------------- PTX helpers (baseline sm_80+ features only) ----------
__device__ __forceinline__ uint32_t smem_u32(const void* p) {
    uint32_t a;
    asm("{ .reg .u64 t; cvta.to.shared.u64 t, %1; cvt.u32.u64 %0, t; }"
        : "=r"(a) : "l"(p));
    return a;
}
__device__ __forceinline__ void cp_async16(uint32_t dst, const void* src) {
    asm volatile("cp.async.cg.shared.global [%0], [%1], 16;"
                 :: "r"(dst), "l"(src) : "memory");
}
__device__ __forceinline__ void cp_commit() {
    asm volatile("cp.async.commit_group;" ::: "memory");
}
__device__ __forceinline__ void ldsm4(uint32_t& r0, uint32_t& r1, uint32_t& r2,
                                      uint32_t& r3, uint32_t addr) {
    asm volatile("ldmatrix.sync.aligned.m8n8.x4.shared.b16 {%0,%1,%2,%3}, [%4];"
                 : "=r"(r0), "=r"(r1), "=r"(r2), "=r"(r3) : "r"(addr));
}
__device__ __forceinline__ void ldsm4t(uint32_t& r0, uint32_t& r1, uint32_t& r2,
                                       uint32_t& r3, uint32_t addr) {
    asm volatile("ldmatrix.sync.aligned.m8n8.x4.trans.shared.b16 {%0,%1,%2,%3}, [%4];"
                 : "=r"(r0), "=r"(r1), "=r"(r2), "=r"(r3) : "r"(addr));
}
__device__ __forceinline__ void mma16816(float* d, const uint32_t* a,
                                         uint32_t b0, uint32_t b1) {
    asm volatile(
        "mma.sync.aligned.m16n8k16.row.col.f32.bf16.bf16.f32 "
        "{%0,%1,%2,%3}, {%4,%5,%6,%7}, {%8,%9}, {%0,%1,%2,%3};"
        : "+f"(d[0]), "+f"(d[1]), "+f"(d[2]), "+f"(d[3])
        : "r"(a[0]), "r"(a[1]), "r"(a[2]), "r"(a[3]), "r"(b0), "r"(b1));
}

// ---------------------------------------------------------------------------
// prep: blocks [0,512): masked agg -> A_hi/A_lo (2 blocks per sample, active-
//       index list instead of per-element ffs);
//       blocks [512,2560): streaming W fp32 -> bf16 hi/lo convert (NO transpose
//       -- the GEMM consumes W[k][n] via ldmatrix.trans).
// ---------------------------------------------------------------------------
static constexpr int AGG_BLKS = 512;         // 2 per sample
static constexpr int CVT_BLKS = 2048;        // (Dd*Dd/4) / (256*2)

__global__ __launch_bounds__(256) void prep_kernel(
    const float* __restrict__ feat,
    const void* __restrict__ label_raw,
    const float* __restrict__ W)
{
    int bid = blockIdx.x;

    if (bid < AGG_BLKS) {
        __shared__ int s_idx[32];
        __shared__ int s_n;
        int b = bid >> 1;
        int half = bid & 1;

        if (threadIdx.x < 32) {
            // int64 labels (values 0/1) have all odd 32-bit words zero
            const int* l32 = (const int*)label_raw;
            int nz = 0;
            for (int i = threadIdx.x; i < 64; i += 32)
                if (l32[2 * i + 1] != 0) nz = 1;
            unsigned any = __ballot_sync(0xffffffffu, nz);
            int is_i64 = (any == 0u);

            int pred;
            if (is_i64) {
                const long long* l = (const long long*)label_raw;
                pred = (l[(size_t)b * Aa + threadIdx.x] > 0);
            } else {
                const int* l = (const int*)label_raw;
                pred = (l[(size_t)b * Aa + threadIdx.x] > 0);
            }
            unsigned m = __ballot_sync(0xffffffffu, pred);
            if (pred) s_idx[__popc(m & ((1u << threadIdx.x) - 1u))] = threadIdx.x;
            if (threadIdx.x == 0) s_n = __popc(m);
        }
        __syncthreads();
        int nact = s_n;

        const float4* f4 = reinterpret_cast<const float4*>(feat) + (size_t)b * Aa * (Dd / 4);
        __nv_bfloat162* hi2 = reinterpret_cast<__nv_bfloat162*>(g_Ahi + (size_t)b * Dd);
        __nv_bfloat162* lo2 = reinterpret_cast<__nv_bfloat162*>(g_Alo + (size_t)b * Dd);

        int i = half * 256 + threadIdx.x;     // float4 index within row (0..511)
        float4 s = make_float4(0.f, 0.f, 0.f, 0.f);
#pragma unroll 4
        for (int j = 0; j < nact; j++) {
            float4 v = f4[(size_t)s_idx[j] * (Dd / 4) + i];
            s.x += v.x; s.y += v.y; s.z += v.z; s.w += v.w;
        }
        float vals[4] = {s.x, s.y, s.z, s.w};
        __nv_bfloat16 h[4], l[4];
#pragma unroll
        for (int j = 0; j < 4; j++) {
            h[j] = __float2bfloat16(vals[j]);
            l[j] = __float2bfloat16(vals[j] - __bfloat162float(h[j]));
        }
        hi2[i * 2 + 0] = __nv_bfloat162(h[0], h[1]);
        hi2[i * 2 + 1] = __nv_bfloat162(h[2], h[3]);
        lo2[i * 2 + 0] = __nv_bfloat162(l[0], l[1]);
        lo2[i * 2 + 1] = __nv_bfloat162(l[2], l[3]);
    } else {
        // pure streaming convert: 2 float4 per thread
        const float4* W4 = (const float4*)W;
        __nv_bfloat162* hi2 = (__nv_bfloat162*)g_Whi;
        __nv_bfloat162* lo2 = (__nv_bfloat162*)g_Wlo;
        int base = (bid - AGG_BLKS) * 512 + threadIdx.x;
#pragma unroll
        for (int u = 0; u < 2; u++) {
            int i = base + u * 256;
            float4 w = W4[i];
            float vals[4] = {w.x, w.y, w.z, w.w};
            __nv_bfloat16 h[4], l[4];
#pragma unroll
            for (int j = 0; j < 4; j++) {
                h[j] = __float2bfloat16(vals[j]);
                l[j] = __float2bfloat16(vals[j] - __bfloat162float(h[j]));
            }
            hi2[i * 2 + 0] = __nv_bfloat162(h[0], h[1]);
            hi2[i * 2 + 1] = __nv_bfloat162(h[2], h[3]);
            lo2[i * 2 + 0] = __nv_bfloat162(l[0], l[1]);
            lo2[i * 2 + 1] = __nv_bfloat162(l[2], l[3]);
        }
    }
}

// ---------------------------------------------------------------------------
// bf16 GEMM via mma.sync, ONE split-term per CTA.z -> fp32 partials.
// CTA tile 64x64, 8 warps = 2(m) x 2(n) x 2(k16-split). 64 chunks of k32,
// 4-stage cp.async pipeline, one commit-group per iteration (empty in tail).
// A SMEM: [m64][k32] 64B rows (as before). B SMEM: [k32][n64] 128B rows,
// consumed via ldmatrix.x4.trans (W stays in native [k][n] layout globally).
// Grid 32x4x3 = 384 CTAs.
// ---------------------------------------------------------------------------
static constexpr int STAGE_BYTES = 8192;     // A 4KB + B 4KB
static constexpr int NSTAGE = 4;
static constexpr int NCHUNK = 64;            // 2048 / 32

__global__ __launch_bounds__(256, 1) void gemm_kernel() {
    __shared__ __align__(128) char smbuf[NSTAGE * STAGE_BYTES];   // 32 KB
    const uint32_t sbase = smem_u32(smbuf);

    const int tid = threadIdx.x;
    const int lane = tid & 31;
    const int wid = tid >> 5;
    const int kw = wid >> 2;          // k16 half (0/1)
    const int wm = (wid >> 1) & 1;    // warp m
    const int wn = wid & 1;           // warp n

    const int m0 = blockIdx.y * 64;
    const int n0 = blockIdx.x * 64;
    const int term = blockIdx.z;      // 0: Ahi*Whi, 1: Ahi*Wlo, 2: Alo*Whi

    const __nv_bfloat16* Ap = (term == 2) ? g_Alo : g_Ahi;
    const __nv_bfloat16* Bp = (term == 1) ? g_Wlo : g_Whi;
    const __nv_bfloat16* Ag = Ap + (size_t)m0 * Dd;           // [m][k]
    const __nv_bfloat16* Bg = Bp + n0;                        // [k][n] col slice

    // ldmatrix A offsets (within stage A region): rows 64B, swizzle c^((row>>1)&3)
    const int g = lane >> 3;
    const int lr = lane & 7;
    uint32_t offA[2];
#pragma unroll
    for (int mt = 0; mt < 2; mt++) {
        int row = wm * 32 + mt * 16 + (g & 1) * 8 + lr;
        int c = 2 * kw + (g >> 1);
        offA[mt] = row * 64 + ((c ^ ((row >> 1) & 3)) << 4);
    }
    // ldmatrix B offsets (trans): stored [k32][n64], rows 128B, swizzle c^(row&7)
    // x4 groups: j0=(k+0..7, ng), j1=(k+8..15, ng), j2=(k+0..7, ng+1), j3=(k+8..15, ng+1)
    uint32_t offB[2];
#pragma unroll
    for (int p = 0; p < 2; p++) {
        int krow = kw * 16 + (g & 1) * 8 + lr;
        int c = wn * 4 + 2 * p + (g >> 1);             // 16B chunk = 8 n-cols
        offB[p] = krow * 128 + ((c ^ (krow & 7)) << 4);
    }

    // cp.async assignments
    const int arow = tid >> 2, ac = tid & 3;           // A: 64 rows x 4 chunks
    const uint32_t aoff = arow * 64 + ((ac ^ ((arow >> 1) & 3)) << 4);
    const int brow = tid >> 3, bc = tid & 7;           // B: 32 rows x 8 chunks
    const uint32_t boff = brow * 128 + ((bc ^ (brow & 7)) << 4);

    auto issue_load = [&](int chunk) {
        int kt = chunk * 32;
        uint32_t st = sbase + (chunk & (NSTAGE - 1)) * STAGE_BYTES;
        cp_async16(st + aoff, Ag + (size_t)arow * Dd + kt + ac * 8);
        cp_async16(st + 4096 + boff, Bg + (size_t)(kt + brow) * Dd + bc * 8);
        cp_commit();
    };

    float acc[2][4][4];
#pragma unroll
    for (int mt = 0; mt < 2; mt++)
#pragma unroll
        for (int nf = 0; nf < 4; nf++)
#pragma unroll
            for (int k = 0; k < 4; k++) acc[mt][nf][k] = 0.f;

    issue_load(0); issue_load(1); issue_load(2);

    for (int i = 0; i < NCHUNK; i++) {
        // chunk i's group was committed 3 iterations ago; with exactly one
        // commit per iteration, wait_group 2 guarantees stage i has landed.
        asm volatile("cp.async.wait_group 2;" ::: "memory");
        __syncthreads();
        if (i + 3 < NCHUNK) issue_load(i + 3);
        else cp_commit();                      // empty group keeps accounting exact

        uint32_t sA = sbase + (i & (NSTAGE - 1)) * STAGE_BYTES;
        uint32_t sB = sA + 4096;

        uint32_t a[2][4], b[2][4];
        ldsm4(a[0][0], a[0][1], a[0][2], a[0][3], sA + offA[0]);
        ldsm4(a[1][0], a[1][1], a[1][2], a[1][3], sA + offA[1]);
        ldsm4t(b[0][0], b[0][1], b[0][2], b[0][3], sB + offB[0]);
        ldsm4t(b[1][0], b[1][1], b[1][2], b[1][3], sB + offB[1]);

#pragma unroll
        for (int mt = 0; mt < 2; mt++) {
            mma16816(acc[mt][0], a[mt], b[0][0], b[0][1]);
            mma16816(acc[mt][1], a[mt], b[0][2], b[0][3]);
            mma16816(acc[mt][2], a[mt], b[1][0], b[1][1]);
            mma16816(acc[mt][3], a[mt], b[1][2], b[1][3]);
        }
    }
    asm volatile("cp.async.wait_group 0;" ::: "memory");
    __syncthreads();

    // split-k reduce through SMEM, then write fp32 partial for this term
    float* smf = (float*)smbuf;
    const int region = (wm * 2 + wn) * 1024;           // 32x32 floats per warp-pair
    float* gp = g_part[term];

    if (kw == 1) {
#pragma unroll
        for (int mt = 0; mt < 2; mt++)
#pragma unroll
            for (int nf = 0; nf < 4; nf++) {
                int lrow = mt * 16 + (lane >> 2);
                int lcol = nf * 8 + (lane & 3) * 2;
                smf[region + lrow * 32 + lcol + 0] = acc[mt][nf][0];
                smf[region + lrow * 32 + lcol + 1] = acc[mt][nf][1];
                smf[region + (lrow + 8) * 32 + lcol + 0] = acc[mt][nf][2];
                smf[region + (lrow + 8) * 32 + lcol + 1] = acc[mt][nf][3];
            }
    }
    __syncthreads();
    if (kw == 0) {
#pragma unroll
        for (int mt = 0; mt < 2; mt++)
#pragma unroll
            for (int nf = 0; nf < 4; nf++) {
                int lrow = mt * 16 + (lane >> 2);
                int lcol = nf * 8 + (lane & 3) * 2;
                int grow = m0 + wm * 32 + lrow;
                int gcol = n0 + wn * 32 + lcol;

                float2 r0, r1;
                r0.x = acc[mt][nf][0] + smf[region + lrow * 32 + lcol + 0];
                r0.y = acc[mt][nf][1] + smf[region + lrow * 32 + lcol + 1];
                r1.x = acc[mt][nf][2] + smf[region + (lrow + 8) * 32 + lcol + 0];
                r1.y = acc[mt][nf][3] + smf[region + (lrow + 8) * 32 + lcol + 1];
                *(float2*)&gp[(size_t)grow * Dd + gcol] = r0;
                *(float2*)&gp[(size_t)(grow + 8) * Dd + gcol] = r1;
            }
    }
}

// ---------------------------------------------------------------------------
// finish: out = tanh(p0 + p1 + p2 + bias)
// ---------------------------------------------------------------------------
__global__ __launch_bounds__(256) void finish_kernel(
    const float* __restrict__ bias, float* __restrict__ out)
{
    int idx = blockIdx.x * 256 + threadIdx.x;        // float4 index
    const float4* p0 = (const float4*)g_part[0];
    const float4* p1 = (const float4*)g_part[1];
    const float4* p2 = (const float4*)g_part[2];
    int n4 = idx & (Dd / 4 - 1);
    float4 a = p0[idx], b = p1[idx], c = p2[idx];
    float4 bv = ((const float4*)bias)[n4];
    float4 r;
    r.x = tanhf(a.x + b.x + c.x + bv.x);
    r.y = tanhf(a.y + b.y + c.y + bv.y);
    r.z = tanhf(a.z + b.z + c.z + bv.z);
    r.w = tanhf(a.w + b.w + c.w + bv.w);
    ((float4*)out)[idx] = r;
}

// ---------------------------------------------------------------------------
// launch: inputs x, attribute_feat, attribute_label, W, b  (x unused: adj[A][A]=0)
// ---------------------------------------------------------------------------
extern "C" void kernel_launch(void* const* d_in, const int* in_sizes, int n_in,
                              void* d_out, int out_size) {
    (void)in_sizes; (void)n_in; (void)out_size;
    const float* feat  = (const float*)d_in[1];
    const void*  label = d_in[2];
    const float* W     = (const float*)d_in[3];
    const float* bias  = (const float*)d_in[4];
    float* out = (float*)d_out;

    prep_kernel<<<AGG_BLKS + CVT_BLKS, 256>>>(feat, label, W);
    gemm_kernel<<<dim3(Dd / 64, Bb / 64, 3), 256>>>();
    finish_kernel<<<(Bb * Dd / 4) / 256, 256>>>(bias, out);
}